// round 1
// baseline (speedup 1.0000x reference)
#include <cuda_runtime.h>

#define DHID   128
#define NB     4
#define NN_MAX 100096   // 782 * 128, covers N_NODES = 100000

// Scratch: basis projections xb[n][b][o] and in-degree counts.
__device__ float g_xb[(size_t)NN_MAX * NB * DHID];   // ~205 MB
__device__ float g_cnt[NN_MAX];

#define APITCH 132   // float4-aligned pitch (132*4 % 16 == 0)

// ---------------------------------------------------------------------------
// Kernel 1: xb[n, b*128+o] = sum_k emb[h[n], k] * weight[b, k, o]
// One block = 128 nodes x 128 outputs for one basis b. 256 threads, 8x8 micro.
// ---------------------------------------------------------------------------
__global__ __launch_bounds__(256, 1) void rgcn_gemm_kernel(
    const int*   __restrict__ h,
    const float* __restrict__ emb,
    const float* __restrict__ weight,
    int n_nodes)
{
    __shared__ float As[128][APITCH];  // [m][k]
    __shared__ float Bs[128][128];     // [k][n]

    const int b    = blockIdx.y;
    const int m0   = blockIdx.x * 128;
    const int tid  = threadIdx.x;
    const int lane = tid & 31;
    const int wid  = tid >> 5;

    const float* wb = weight + (size_t)b * DHID * DHID;

    // Cooperative load: each of 8 warps loads rows (it*8 + wid), 128 floats/row.
    #pragma unroll
    for (int it = 0; it < 16; ++it) {
        int m = it * 8 + wid;
        int node = m0 + m;
        float4 v = make_float4(0.f, 0.f, 0.f, 0.f);
        if (node < n_nodes) {
            int hn = __ldg(&h[node]);
            v = *reinterpret_cast<const float4*>(emb + (size_t)hn * DHID + lane * 4);
        }
        *reinterpret_cast<float4*>(&As[m][lane * 4]) = v;
        *reinterpret_cast<float4*>(&Bs[m][lane * 4]) =
            *reinterpret_cast<const float4*>(wb + m * DHID + lane * 4);
    }
    __syncthreads();

    const int tx = tid & 15;   // output-col group
    const int ty = tid >> 4;   // node-row group

    float acc[8][8];
    #pragma unroll
    for (int i = 0; i < 8; ++i)
        #pragma unroll
        for (int j = 0; j < 8; ++j) acc[i][j] = 0.f;

    #pragma unroll 4
    for (int k = 0; k < 128; ++k) {
        float a[8], bb[8];
        #pragma unroll
        for (int i = 0; i < 8; ++i) a[i] = As[ty * 8 + i][k];   // broadcast reads
        *reinterpret_cast<float4*>(bb)     = *reinterpret_cast<const float4*>(&Bs[k][tx * 8]);
        *reinterpret_cast<float4*>(bb + 4) = *reinterpret_cast<const float4*>(&Bs[k][tx * 8 + 4]);
        #pragma unroll
        for (int i = 0; i < 8; ++i)
            #pragma unroll
            for (int j = 0; j < 8; ++j)
                acc[i][j] = fmaf(a[i], bb[j], acc[i][j]);
    }

    #pragma unroll
    for (int i = 0; i < 8; ++i) {
        int node = m0 + ty * 8 + i;
        if (node < n_nodes) {
            float* op = g_xb + (size_t)node * (NB * DHID) + b * DHID + tx * 8;
            *reinterpret_cast<float4*>(op)     = make_float4(acc[i][0], acc[i][1], acc[i][2], acc[i][3]);
            *reinterpret_cast<float4*>(op + 4) = make_float4(acc[i][4], acc[i][5], acc[i][6], acc[i][7]);
        }
    }
}

// ---------------------------------------------------------------------------
// Kernel 2: zero the output accumulator and counts.
// ---------------------------------------------------------------------------
__global__ void rgcn_init_kernel(float* __restrict__ out, int n_nodes)
{
    int i = blockIdx.x * blockDim.x + threadIdx.x;
    if (i < n_nodes * DHID) out[i] = 0.f;
    if (i < n_nodes)        g_cnt[i] = 0.f;
}

// ---------------------------------------------------------------------------
// Kernel 3: one warp per edge.
//   msg = norm * sum_b coeff[b] * xb[src, b, :]; red-add into out[dst].
// ---------------------------------------------------------------------------
__global__ __launch_bounds__(256) void rgcn_edge_kernel(
    const int*   __restrict__ r,
    const float* __restrict__ norm,
    const int*   __restrict__ src,
    const int*   __restrict__ dst,
    const float* __restrict__ w_comp,
    float*       __restrict__ out,
    int n_edges)
{
    int e    = (blockIdx.x * blockDim.x + threadIdx.x) >> 5;
    int lane = threadIdx.x & 31;
    if (e >= n_edges) return;

    int   s   = __ldg(src + e);
    int   d   = __ldg(dst + e);
    int   rel = __ldg(r + e);
    float nm  = __ldg(norm + e);
    float4 c  = __ldg(reinterpret_cast<const float4*>(w_comp) + rel);  // 4 basis coeffs

    const float4* xp = reinterpret_cast<const float4*>(g_xb) + (size_t)s * (NB * DHID / 4) + lane;
    float4 v0 = __ldg(xp);        // basis 0, dims [4*lane, 4*lane+4)
    float4 v1 = __ldg(xp + 32);   // basis 1
    float4 v2 = __ldg(xp + 64);   // basis 2
    float4 v3 = __ldg(xp + 96);   // basis 3

    float4 m;
    m.x = nm * (c.x * v0.x + c.y * v1.x + c.z * v2.x + c.w * v3.x);
    m.y = nm * (c.x * v0.y + c.y * v1.y + c.z * v2.y + c.w * v3.y);
    m.z = nm * (c.x * v0.z + c.y * v1.z + c.z * v2.z + c.w * v3.z);
    m.w = nm * (c.x * v0.w + c.y * v1.w + c.z * v2.w + c.w * v3.w);

    float* op = out + (size_t)d * DHID + lane * 4;
    asm volatile("red.global.add.v4.f32 [%0], {%1, %2, %3, %4};"
                 :: "l"(op), "f"(m.x), "f"(m.y), "f"(m.z), "f"(m.w) : "memory");

    if (lane == 0) atomicAdd(&g_cnt[d], 1.0f);
}

// ---------------------------------------------------------------------------
// Kernel 4: out = out / max(cnt, 1) + bias
// ---------------------------------------------------------------------------
__global__ void rgcn_final_kernel(float* __restrict__ out,
                                  const float* __restrict__ bias,
                                  int n_nodes)
{
    int i = blockIdx.x * blockDim.x + threadIdx.x;
    if (i >= n_nodes * DHID) return;
    int node = i >> 7;
    float c = g_cnt[node];
    out[i] = out[i] / fmaxf(c, 1.0f) + bias[i & (DHID - 1)];
}

// ---------------------------------------------------------------------------
// Inputs (metadata order): h, r, norm, src, dst, emb_table, weight, w_comp, h_bias
// ---------------------------------------------------------------------------
extern "C" void kernel_launch(void* const* d_in, const int* in_sizes, int n_in,
                              void* d_out, int out_size)
{
    const int*   h      = (const int*)  d_in[0];
    const int*   r      = (const int*)  d_in[1];
    const float* norm   = (const float*)d_in[2];
    const int*   src    = (const int*)  d_in[3];
    const int*   dst    = (const int*)  d_in[4];
    const float* emb    = (const float*)d_in[5];
    const float* weight = (const float*)d_in[6];
    const float* w_comp = (const float*)d_in[7];
    const float* bias   = (const float*)d_in[8];

    int n_nodes = in_sizes[0];
    int n_edges = in_sizes[1];
    float* out = (float*)d_out;

    // 1) basis projections
    dim3 ggrid((n_nodes + 127) / 128, NB);
    rgcn_gemm_kernel<<<ggrid, 256>>>(h, emb, weight, n_nodes);

    // 2) zero accumulators
    int init_elems = n_nodes * DHID;
    rgcn_init_kernel<<<(init_elems + 255) / 256, 256>>>(out, n_nodes);

    // 3) per-edge message + scatter
    int nwarps = n_edges;                 // one warp per edge
    rgcn_edge_kernel<<<(nwarps + 7) / 8, 256>>>(r, norm, src, dst, w_comp, out, n_edges);

    // 4) mean + bias
    rgcn_final_kernel<<<(init_elems + 255) / 256, 256>>>(out, bias, n_nodes);
}

// round 3
// speedup vs baseline: 2.6586x; 2.6586x over previous
#include <cuda_runtime.h>
#include <cuda_fp16.h>
#include <cstdint>

#define DHID   128
#define NB     4
#define NN_MAX 100096

// Scratch: fp16 basis projections xb[node][b*128+o] (~102 MB), degree counts,
// transposed fp16 weights Wt[b][o][k].
__device__ __half g_xb[(size_t)NN_MAX * NB * DHID];
__device__ float  g_cnt[NN_MAX];
__device__ __half g_wt[NB * DHID * DHID];

#define KP 136  // smem row pitch in fp16 (272B: 16B-aligned, conflict-free ldmatrix)

// ---------------------------------------------------------------------------
// Prep: weight[b][k][o] fp32 -> g_wt[b][o][k] fp16 (transposed for col-major B)
// ---------------------------------------------------------------------------
__global__ void rgcn_prep_w(const float* __restrict__ weight)
{
    int idx = blockIdx.x * blockDim.x + threadIdx.x;
    if (idx >= NB * DHID * DHID) return;
    int b = idx >> 14;
    int k = (idx >> 7) & 127;
    int o = idx & 127;
    g_wt[(b * DHID + o) * DHID + k] = __float2half_rn(weight[idx]);
}

// ---------------------------------------------------------------------------
// GEMM: block = 128 nodes x 512 outputs (4 bases x 128), HMMA m16n8k16.
// 256 threads = 8 warps, warp tile 32(M) x 64(N). A resident; loop bases.
// ---------------------------------------------------------------------------
__device__ __forceinline__ uint32_t smem_u32(const void* p) {
    uint32_t a;
    asm("{ .reg .u64 t; cvta.to.shared.u64 t, %1; cvt.u32.u64 %0, t; }" : "=r"(a) : "l"(p));
    return a;
}
__device__ __forceinline__ void ldsm_x4(uint32_t* r, uint32_t addr) {
    asm volatile("ldmatrix.sync.aligned.m8n8.x4.shared.b16 {%0,%1,%2,%3}, [%4];"
                 : "=r"(r[0]), "=r"(r[1]), "=r"(r[2]), "=r"(r[3]) : "r"(addr));
}
__device__ __forceinline__ void ldsm_x2(uint32_t* r, uint32_t addr) {
    asm volatile("ldmatrix.sync.aligned.m8n8.x2.shared.b16 {%0,%1}, [%2];"
                 : "=r"(r[0]), "=r"(r[1]) : "r"(addr));
}
__device__ __forceinline__ void mma16816(float* c, const uint32_t* a, const uint32_t* b) {
    asm volatile(
        "mma.sync.aligned.m16n8k16.row.col.f32.f16.f16.f32 "
        "{%0,%1,%2,%3}, {%4,%5,%6,%7}, {%8,%9}, {%0,%1,%2,%3};"
        : "+f"(c[0]), "+f"(c[1]), "+f"(c[2]), "+f"(c[3])
        : "r"(a[0]), "r"(a[1]), "r"(a[2]), "r"(a[3]), "r"(b[0]), "r"(b[1]));
}

#define SMEM_BYTES ((128 * KP * 2) * 2)   // A tile + B tile, fp16

__global__ __launch_bounds__(256) void rgcn_gemm_mma(
    const int*   __restrict__ h,
    const float* __restrict__ emb,
    int n_nodes)
{
    extern __shared__ __align__(16) __half smem[];
    __half* As = smem;              // [128][KP]
    __half* Bs = smem + 128 * KP;   // [128][KP]  (Wt rows: o, cols: k)

    const int tid  = threadIdx.x;
    const int lane = tid & 31;
    const int wrp  = tid >> 5;
    const int wm   = (wrp & 3) * 32;   // warp M offset (rows/nodes)
    const int wn   = (wrp >> 2) * 64;  // warp N offset (output cols)
    const int m0   = blockIdx.x * 128;

    // --- Load A: gather emb rows via h, fp32->fp16, padded row-major smem ---
    #pragma unroll
    for (int it = 0; it < 16; ++it) {
        int idx  = it * 256 + tid;       // 4096 = 128 rows x 32 quads
        int m    = idx >> 5;
        int kc   = (idx & 31) * 4;
        int node = m0 + m;
        float4 v = make_float4(0.f, 0.f, 0.f, 0.f);
        if (node < n_nodes) {
            int hn = __ldg(h + node);
            v = *reinterpret_cast<const float4*>(emb + (size_t)hn * DHID + kc);
        }
        __half2 p0 = __floats2half2_rn(v.x, v.y);
        __half2 p1 = __floats2half2_rn(v.z, v.w);
        uint2 pk;
        pk.x = *reinterpret_cast<uint32_t*>(&p0);
        pk.y = *reinterpret_cast<uint32_t*>(&p1);
        *reinterpret_cast<uint2*>(As + m * KP + kc) = pk;
    }

    // ldmatrix source addresses (A fixed across bases)
    uint32_t as_base = smem_u32(As);
    uint32_t bs_base = smem_u32(Bs);
    // A frag addr for (mi, kk): row = wm + mi*16 + (lane&15), col = kk*16 + 8*(lane>>4)
    const int arow = (lane & 15);
    const int acol8 = 8 * (lane >> 4);
    // B frag addr for (ni, kk): row(o) = wn + ni*8 + (lane&7), col = kk*16 + 8*((lane>>3)&1)
    const int brow = (lane & 7);
    const int bcol8 = 8 * ((lane >> 3) & 1);

    const int gq = lane >> 2;        // output row within 16
    const int tg = lane & 3;         // output col pair

    for (int b = 0; b < NB; ++b) {
        // --- Load B tile: Wt[b][o][k] -> Bs[o][k] padded ---
        __syncthreads();   // protect Bs from previous iteration's readers
        const uint4* wsrc = reinterpret_cast<const uint4*>(g_wt + b * DHID * DHID);
        #pragma unroll
        for (int it = 0; it < 8; ++it) {
            int idx = it * 256 + tid;     // 2048 uint4 = 128 rows x 16
            int o   = idx >> 4;
            int kq  = (idx & 15) * 8;     // fp16 col
            *reinterpret_cast<uint4*>(Bs + o * KP + kq) = wsrc[idx];
        }
        __syncthreads();

        float acc[2][8][4];
        #pragma unroll
        for (int mi = 0; mi < 2; ++mi)
            #pragma unroll
            for (int ni = 0; ni < 8; ++ni)
                #pragma unroll
                for (int q = 0; q < 4; ++q) acc[mi][ni][q] = 0.f;

        #pragma unroll
        for (int kk = 0; kk < 8; ++kk) {
            uint32_t af[2][4], bf[8][2];
            #pragma unroll
            for (int mi = 0; mi < 2; ++mi)
                ldsm_x4(af[mi], as_base + ((wm + mi * 16 + arow) * KP + kk * 16 + acol8) * 2);
            #pragma unroll
            for (int ni = 0; ni < 8; ++ni)
                ldsm_x2(bf[ni], bs_base + ((wn + ni * 8 + brow) * KP + kk * 16 + bcol8) * 2);
            #pragma unroll
            for (int mi = 0; mi < 2; ++mi)
                #pragma unroll
                for (int ni = 0; ni < 8; ++ni)
                    mma16816(acc[mi][ni], af[mi], bf[ni]);
        }

        // --- Epilogue: fp32 -> fp16, store to g_xb[node][b*128 + col] ---
        #pragma unroll
        for (int mi = 0; mi < 2; ++mi) {
            int node0 = m0 + wm + mi * 16 + gq;
            #pragma unroll
            for (int half_ = 0; half_ < 2; ++half_) {
                int node = node0 + half_ * 8;
                if (node < n_nodes) {
                    __half* orow = g_xb + (size_t)node * (NB * DHID) + b * DHID + wn + tg * 2;
                    #pragma unroll
                    for (int ni = 0; ni < 8; ++ni) {
                        __half2 v = __floats2half2_rn(acc[mi][ni][half_ * 2],
                                                      acc[mi][ni][half_ * 2 + 1]);
                        *reinterpret_cast<__half2*>(orow + ni * 8) = v;
                    }
                }
            }
        }
    }
}

// ---------------------------------------------------------------------------
// Init: zero out + counts (float4)
// ---------------------------------------------------------------------------
__global__ void rgcn_init_kernel(float* __restrict__ out, int n_nodes)
{
    int i = blockIdx.x * blockDim.x + threadIdx.x;
    if (i < n_nodes * (DHID / 4))
        reinterpret_cast<float4*>(out)[i] = make_float4(0.f, 0.f, 0.f, 0.f);
    if (i < n_nodes) g_cnt[i] = 0.f;
}

// ---------------------------------------------------------------------------
// Edge: one warp per edge; fp16 xb gather, basis combine, red.v4 scatter
// ---------------------------------------------------------------------------
__global__ __launch_bounds__(256) void rgcn_edge_kernel(
    const int*   __restrict__ r,
    const float* __restrict__ norm,
    const int*   __restrict__ src,
    const int*   __restrict__ dst,
    const float* __restrict__ w_comp,
    float*       __restrict__ out,
    int n_edges)
{
    int e    = (blockIdx.x * blockDim.x + threadIdx.x) >> 5;
    int lane = threadIdx.x & 31;
    if (e >= n_edges) return;

    int   s   = __ldg(src + e);
    int   d   = __ldg(dst + e);
    int   rel = __ldg(r + e);
    float nm  = __ldg(norm + e);
    float4 c  = __ldg(reinterpret_cast<const float4*>(w_comp) + rel);

    const uint2* xp = reinterpret_cast<const uint2*>(g_xb + (size_t)s * (NB * DHID)) + lane;
    uint2 q0 = __ldg(xp);
    uint2 q1 = __ldg(xp + 32);
    uint2 q2 = __ldg(xp + 64);
    uint2 q3 = __ldg(xp + 96);

    float2 a0 = __half22float2(*reinterpret_cast<__half2*>(&q0.x));
    float2 a1 = __half22float2(*reinterpret_cast<__half2*>(&q0.y));
    float2 b0 = __half22float2(*reinterpret_cast<__half2*>(&q1.x));
    float2 b1 = __half22float2(*reinterpret_cast<__half2*>(&q1.y));
    float2 c0 = __half22float2(*reinterpret_cast<__half2*>(&q2.x));
    float2 c1 = __half22float2(*reinterpret_cast<__half2*>(&q2.y));
    float2 d0 = __half22float2(*reinterpret_cast<__half2*>(&q3.x));
    float2 d1 = __half22float2(*reinterpret_cast<__half2*>(&q3.y));

    float4 m;
    m.x = nm * (c.x * a0.x + c.y * b0.x + c.z * c0.x + c.w * d0.x);
    m.y = nm * (c.x * a0.y + c.y * b0.y + c.z * c0.y + c.w * d0.y);
    m.z = nm * (c.x * a1.x + c.y * b1.x + c.z * c1.x + c.w * d1.x);
    m.w = nm * (c.x * a1.y + c.y * b1.y + c.z * c1.y + c.w * d1.y);

    float* op = out + (size_t)d * DHID + lane * 4;
    asm volatile("red.global.add.v4.f32 [%0], {%1, %2, %3, %4};"
                 :: "l"(op), "f"(m.x), "f"(m.y), "f"(m.z), "f"(m.w) : "memory");

    if (lane == 0) atomicAdd(&g_cnt[d], 1.0f);
}

// ---------------------------------------------------------------------------
// Final: out = out / max(cnt,1) + bias (float4)
// ---------------------------------------------------------------------------
__global__ void rgcn_final_kernel(float* __restrict__ out,
                                  const float* __restrict__ bias,
                                  int n_nodes)
{
    int i = blockIdx.x * blockDim.x + threadIdx.x;
    if (i >= n_nodes * (DHID / 4)) return;
    float rc = 1.0f / fmaxf(g_cnt[i >> 5], 1.0f);
    float4 v = reinterpret_cast<float4*>(out)[i];
    float4 b = reinterpret_cast<const float4*>(bias)[i & 31];
    v.x = v.x * rc + b.x;
    v.y = v.y * rc + b.y;
    v.z = v.z * rc + b.z;
    v.w = v.w * rc + b.w;
    reinterpret_cast<float4*>(out)[i] = v;
}

// ---------------------------------------------------------------------------
// Inputs: h, r, norm, src, dst, emb_table, weight, w_comp, h_bias
// ---------------------------------------------------------------------------
extern "C" void kernel_launch(void* const* d_in, const int* in_sizes, int n_in,
                              void* d_out, int out_size)
{
    const int*   h      = (const int*)  d_in[0];
    const int*   r      = (const int*)  d_in[1];
    const float* norm   = (const float*)d_in[2];
    const int*   src    = (const int*)  d_in[3];
    const int*   dst    = (const int*)  d_in[4];
    const float* emb    = (const float*)d_in[5];
    const float* weight = (const float*)d_in[6];
    const float* w_comp = (const float*)d_in[7];
    const float* bias   = (const float*)d_in[8];

    int n_nodes = in_sizes[0];
    int n_edges = in_sizes[1];
    float* out = (float*)d_out;

    cudaFuncSetAttribute(rgcn_gemm_mma, cudaFuncAttributeMaxDynamicSharedMemorySize, SMEM_BYTES);

    // 0) weight -> transposed fp16
    rgcn_prep_w<<<(NB * DHID * DHID + 255) / 256, 256>>>(weight);

    // 1) zero accumulators
    int v4 = n_nodes * (DHID / 4);
    rgcn_init_kernel<<<(v4 + 255) / 256, 256>>>(out, n_nodes);

    // 2) basis projections on tensor cores (HMMA)
    rgcn_gemm_mma<<<(n_nodes + 127) / 128, 256, SMEM_BYTES>>>(h, emb, n_nodes);

    // 3) per-edge message + scatter
    rgcn_edge_kernel<<<((n_edges * 32) + 255) / 256, 256>>>(r, norm, src, dst, w_comp, out, n_edges);

    // 4) mean + bias
    rgcn_final_kernel<<<(v4 + 255) / 256, 256>>>(out, bias, n_nodes);
}